// round 15
// baseline (speedup 1.0000x reference)
#include <cuda_runtime.h>
#include <cuda_bf16.h>
#include <math.h>
#include <stdint.h>

#define B_    16
#define S_    8192
#define D_    128
#define H_    512
#define NROT  3
#define NMAT  (B_ * NROT)          // 48
#define MATSZ (D_ * D_)            // 16384
#define W2ROWS (NROT * D_ * D_)    // 49152
#define NCHUNK 16

// ---------------- scratch ----------------
__device__ float g_partial[B_ * NCHUNK * D_];
__device__ float g_h[B_ * H_];
__device__ float g_P[B_ * W2ROWS];          // P[b][r]
__device__ float g_Dl[NMAT * MATSZ];        // Delta = expm(g) - I per matrix
__device__ uint32_t g_frag[B_ * 8192];      // bf16 B-fragments of Delta_R per batch

// ---------------- mma.sync / ldmatrix helpers ----------------
__device__ __forceinline__ uint32_t smem_u32(const void* p) {
    uint32_t a;
    asm("{ .reg .u64 t; cvta.to.shared.u64 t, %1; cvt.u32.u64 %0, t; }" : "=r"(a) : "l"(p));
    return a;
}
__device__ __forceinline__ void ldsm_x4(uint32_t* r, uint32_t addr) {
    asm volatile("ldmatrix.sync.aligned.m8n8.x4.shared.b16 {%0,%1,%2,%3}, [%4];"
                 : "=r"(r[0]), "=r"(r[1]), "=r"(r[2]), "=r"(r[3]) : "r"(addr));
}
__device__ __forceinline__ void ldsm_x2_trans(uint32_t* r, uint32_t addr) {
    asm volatile("ldmatrix.sync.aligned.m8n8.x2.trans.shared.b16 {%0,%1}, [%2];"
                 : "=r"(r[0]), "=r"(r[1]) : "r"(addr));
}
__device__ __forceinline__ void mma16816(float* c, const uint32_t* a, const uint32_t* b) {
    asm volatile("mma.sync.aligned.m16n8k16.row.col.f32.bf16.bf16.f32 "
                 "{%0,%1,%2,%3}, {%4,%5,%6,%7}, {%8,%9}, {%0,%1,%2,%3};"
                 : "+f"(c[0]), "+f"(c[1]), "+f"(c[2]), "+f"(c[3])
                 : "r"(a[0]), "r"(a[1]), "r"(a[2]), "r"(a[3]), "r"(b[0]), "r"(b[1]));
}
__device__ __forceinline__ uint32_t pack_bf2(float a, float b) {
    __nv_bfloat162 h = __floats2bfloat162_rn(a, b);
    return *reinterpret_cast<uint32_t*>(&h);
}

#define LDA 136                      // bf16 plane row stride (elements)
// chain/combine smem layout (bytes)
#define CH_AH 0
#define CH_DH 34816
#define CH_AF 69632                  // fp32 [128][128]
#define CH_ST 135168                 // fp32 [128][132]
#define CH_TOTAL 202752
// apply smem
#define AP_FR 0
#define AP_XH 32768
#define AP_TOTAL (32768 + 64 * LDA * 2)   // 50176
#define AP_TILES 8
// pgemm smem: packed h only (stride 260, bank-conflict-free)
#define PG_TOTAL (16 * 260 * 4)          // 16640

// dummy no-op kernel: keeps ncu capture slot on pgemm
__global__ void dummy_kernel() {}

// 16-warp (512 thr) 128x128x128 bf16 MMA: warp tile 32 rows x 32 cols
__device__ __forceinline__ void mma128w16(uint32_t pa, uint32_t pb,
                                          float acc[2][4][4], int lane, int wid) {
    int m0 = (wid & 3) << 5, n0 = (wid >> 2) << 5;
    int arow = lane & 15, acol = (lane >> 4) << 3;
    #pragma unroll
    for (int ks = 0; ks < 8; ks++) {
        int k0 = ks << 4;
        uint32_t a0[4], a1[4];
        ldsm_x4(a0, pa + (uint32_t)(((m0 + arow) * LDA + k0 + acol) << 1));
        ldsm_x4(a1, pa + (uint32_t)(((m0 + 16 + arow) * LDA + k0 + acol) << 1));
        uint32_t bfr[4][2];
        #pragma unroll
        for (int j = 0; j < 4; j++)
            ldsm_x2_trans(bfr[j], pb + (uint32_t)(((k0 + arow) * LDA + n0 + (j << 3)) << 1));
        #pragma unroll
        for (int j = 0; j < 4; j++) {
            mma16816(acc[0][j], a0, bfr[j]);
            mma16816(acc[1][j], a1, bfr[j]);
        }
    }
}

// ---------------- 1) mean over S: 16 chunks x 16 batches ----------------
__global__ void mean_partial_kernel(const float* __restrict__ x) {
    int b = blockIdx.y, chunk = blockIdx.x;
    int t = threadIdx.x, lane = t & 31, grp = t >> 5;
    const float* xp = x + ((size_t)b * S_ + (size_t)chunk * 512 + grp) * D_ + lane * 4;
    float4 s = make_float4(0.f, 0.f, 0.f, 0.f);
    #pragma unroll 8
    for (int i = 0; i < 64; i++) {
        float4 v = *(const float4*)xp;
        s.x += v.x; s.y += v.y; s.z += v.z; s.w += v.w;
        xp += 8 * D_;
    }
    __shared__ float4 red[256];
    red[t] = s;
    __syncthreads();
    if (grp < 4) {
        float4 o = red[t + 128];
        red[t] = make_float4(red[t].x + o.x, red[t].y + o.y, red[t].z + o.z, red[t].w + o.w);
    }
    __syncthreads();
    if (grp < 2) {
        float4 o = red[t + 64];
        red[t] = make_float4(red[t].x + o.x, red[t].y + o.y, red[t].z + o.z, red[t].w + o.w);
    }
    __syncthreads();
    if (grp == 0) {
        float4 o = red[t + 32];
        float4 r = make_float4(red[t].x + o.x, red[t].y + o.y, red[t].z + o.z, red[t].w + o.w);
        *(float4*)&g_partial[(b * NCHUNK + chunk) * D_ + lane * 4] = r;
    }
}

// ---------------- 2) h = gelu(pooled @ W1^T + b1) ----------------
__global__ void h_kernel(const float* __restrict__ W1, const float* __restrict__ b1) {
    int b = blockIdx.x, t = threadIdx.x;
    __shared__ float ps[D_];
    if (t < D_) {
        float s = 0.f;
        #pragma unroll
        for (int c = 0; c < NCHUNK; c++) s += g_partial[(b * NCHUNK + c) * D_ + t];
        ps[t] = s * (1.0f / (float)S_);
    }
    __syncthreads();
    float acc = b1[t];
    const float* w = W1 + (size_t)t * D_;
    #pragma unroll 8
    for (int k = 0; k < D_; k++) acc = fmaf(ps[k], w[k], acc);
    float z = acc;
    g_h[b * H_ + t] = 0.5f * z * (1.0f + erff(z * 0.70710678118654752f));
}

// ---------------- 3) P = W2 @ h^T + b2: gmem-direct A-fragments, no W2 smem ----------------
// W2 has zero reuse -> load A-fragments straight from gmem (coalesced 32B sectors
// per lane-quad), convert to bf16 in-register, MMA. No syncs in the k-loop.
__global__ __launch_bounds__(256) void pgemm_tc_kernel(const float* __restrict__ W2,
                                                       const float* __restrict__ b2) {
    extern __shared__ char smc[];
    uint32_t* hbf = (uint32_t*)smc;
    int t = threadIdx.x, lane = t & 31, wid = t >> 5;
    int row0 = blockIdx.x * 128;

    // h -> packed bf16 pairs: hbf[n*260 + k/2]
    for (int idx = t; idx < 16 * 256; idx += 256) {
        int n = idx >> 8, kp = idx & 255;
        float2 v = *(const float2*)&g_h[n * H_ + kp * 2];
        hbf[n * 260 + kp] = pack_bf2(v.x, v.y);
    }
    __syncthreads();

    int r0 = row0 + wid * 16 + (lane >> 2);
    const float* wrow0 = W2 + (size_t)r0 * H_;
    const float* wrow1 = W2 + (size_t)(r0 + 8) * H_;
    int kc = (lane & 3) << 1;
    int nq = lane >> 2;

    float acc[2][4] = {};

    #pragma unroll 4
    for (int ks = 0; ks < 32; ks++) {
        int k0 = ks << 4;
        float2 w00 = *(const float2*)(wrow0 + k0 + kc);
        float2 w10 = *(const float2*)(wrow1 + k0 + kc);
        float2 w01 = *(const float2*)(wrow0 + k0 + 8 + kc);
        float2 w11 = *(const float2*)(wrow1 + k0 + 8 + kc);
        uint32_t a[4];
        a[0] = pack_bf2(w00.x, w00.y);
        a[1] = pack_bf2(w10.x, w10.y);
        a[2] = pack_bf2(w01.x, w01.y);
        a[3] = pack_bf2(w11.x, w11.y);
        #pragma unroll
        for (int jn = 0; jn < 2; jn++) {
            int n = jn * 8 + nq;
            uint32_t bfr[2];
            bfr[0] = hbf[n * 260 + ks * 8 + (lane & 3)];
            bfr[1] = hbf[n * 260 + ks * 8 + 4 + (lane & 3)];
            mma16816(acc[jn], a, bfr);
        }
    }

    #pragma unroll
    for (int mi = 0; mi < 2; mi++) {
        int r = r0 + mi * 8;
        float bias = b2[r];
        #pragma unroll
        for (int jn = 0; jn < 2; jn++) {
            int b0 = jn * 8 + ((lane & 3) << 1);
            g_P[(size_t)b0 * W2ROWS + r]       = acc[jn][mi * 2]     + bias;
            g_P[(size_t)(b0 + 1) * W2ROWS + r] = acc[jn][mi * 2 + 1] + bias;
        }
    }
}

// ---------------- 4) fused antisym + expm (order-4 Taylor), 512 threads ----------------
__global__ __launch_bounds__(512, 1) void expm_chain_kernel() {
    extern __shared__ char smc[];
    uint32_t sb = smem_u32(smc);
    float* AF = (float*)(smc + CH_AF);
    float* ST = (float*)(smc + CH_ST);
    int t = threadIdx.x, lane = t & 31, wid = t >> 5;
    int m = blockIdx.x;
    int b = m / NROT, i = m - b * NROT;
    const float* P = g_P + (size_t)b * W2ROWS + (size_t)i * MATSZ;

    for (int idx = t; idx < 4096; idx += 512) {
        int row = idx >> 5, c0 = (idx & 31) << 2;
        *(float4*)(ST + row * 132 + c0) = *(const float4*)(P + (row << 7) + c0);
    }
    __syncthreads();
    for (int idx = t; idx < 16384; idx += 512) {
        int d = idx >> 7, e = idx & 127;
        float v = (ST[d * 132 + e] - ST[e * 132 + d]) * 0.5f;
        AF[(d << 7) + e] = v;
        int eo = (d * LDA + e) << 1;
        *(__nv_bfloat16*)(smc + CH_AH + eo) = __float2bfloat16(v);
        *(__nv_bfloat16*)(smc + CH_DH + eo) = __float2bfloat16(v * 0.25f);
    }
    __syncthreads();

    int m0 = (wid & 3) << 5, n0 = (wid >> 2) << 5;

    #pragma unroll 1
    for (int step = 0; step < 3; step++) {
        float invc = (step == 0) ? (1.f / 3.f) : (step == 1 ? 0.5f : 1.0f);
        float acc[2][4][4];
        #pragma unroll
        for (int mi = 0; mi < 2; mi++)
            #pragma unroll
            for (int j = 0; j < 4; j++)
                #pragma unroll
                for (int q = 0; q < 4; q++) acc[mi][j][q] = 0.f;
        mma128w16(sb + CH_AH, sb + CH_DH, acc, lane, wid);
        __syncthreads();
        #pragma unroll
        for (int mi = 0; mi < 2; mi++)
            #pragma unroll
            for (int j = 0; j < 4; j++) {
                int r = m0 + (mi << 4) + (lane >> 2);
                int c = n0 + (j << 3) + ((lane & 3) << 1);
                float v0 = (AF[(r << 7) + c]           + acc[mi][j][0]) * invc;
                float v1 = (AF[(r << 7) + c + 1]       + acc[mi][j][1]) * invc;
                float v2 = (AF[((r + 8) << 7) + c]     + acc[mi][j][2]) * invc;
                float v3 = (AF[((r + 8) << 7) + c + 1] + acc[mi][j][3]) * invc;
                if (step < 2) {
                    *(uint32_t*)(smc + CH_DH + ((r * LDA + c) << 1))       = pack_bf2(v0, v1);
                    *(uint32_t*)(smc + CH_DH + (((r + 8) * LDA + c) << 1)) = pack_bf2(v2, v3);
                } else {
                    *(float2*)(ST + r * 132 + c)       = make_float2(v0, v1);
                    *(float2*)(ST + (r + 8) * 132 + c) = make_float2(v2, v3);
                }
            }
        __syncthreads();
    }

    float* out = g_Dl + (size_t)m * MATSZ;
    for (int idx = t; idx < 4096; idx += 512) {
        int row = idx >> 5, c0 = (idx & 31) << 2;
        *(float4*)(out + (row << 7) + c0) = *(const float4*)(ST + row * 132 + c0);
    }
}

// ---------------- 5) combine (512 threads): Delta_R; emit frags ----------------
__global__ __launch_bounds__(512, 1) void combine_kernel() {
    extern __shared__ char smc[];
    uint32_t sb = smem_u32(smc);
    float* AF = (float*)(smc + CH_AF);
    float* ST = (float*)(smc + CH_ST);
    int t = threadIdx.x, lane = t & 31, wid = t >> 5;
    int b = blockIdx.x;
    int m0 = (wid & 3) << 5, n0 = (wid >> 2) << 5;

    {
        const float* D0 = g_Dl + (size_t)(b * 3 + 0) * MATSZ;
        const float* D1 = g_Dl + (size_t)(b * 3 + 1) * MATSZ;
        for (int idx = t; idx < 4096; idx += 512) {
            int row = idx >> 5, c0 = (idx & 31) << 2;
            int eo = (row * LDA + c0) << 1;
            float4 v0 = *(const float4*)(D0 + (row << 7) + c0);
            *(float4*)(AF + (row << 7) + c0) = v0;
            *(uint32_t*)(smc + CH_AH + eo)     = pack_bf2(v0.x, v0.y);
            *(uint32_t*)(smc + CH_AH + eo + 4) = pack_bf2(v0.z, v0.w);
            float4 v1 = *(const float4*)(D1 + (row << 7) + c0);
            *(float4*)(ST + row * 132 + c0) = v1;
            *(uint32_t*)(smc + CH_DH + eo)     = pack_bf2(v1.x, v1.y);
            *(uint32_t*)(smc + CH_DH + eo + 4) = pack_bf2(v1.z, v1.w);
        }
        __syncthreads();
        float acc[2][4][4];
        #pragma unroll
        for (int mi = 0; mi < 2; mi++)
            #pragma unroll
            for (int j = 0; j < 4; j++)
                #pragma unroll
                for (int q = 0; q < 4; q++) acc[mi][j][q] = 0.f;
        mma128w16(sb + CH_AH, sb + CH_DH, acc, lane, wid);
        __syncthreads();
        #pragma unroll
        for (int mi = 0; mi < 2; mi++)
            #pragma unroll
            for (int j = 0; j < 4; j++) {
                int r = m0 + (mi << 4) + (lane >> 2);
                int c = n0 + (j << 3) + ((lane & 3) << 1);
                float v0 = ST[r * 132 + c]           + AF[(r << 7) + c]           + acc[mi][j][0];
                float v1 = ST[r * 132 + c + 1]       + AF[(r << 7) + c + 1]       + acc[mi][j][1];
                float v2 = ST[(r + 8) * 132 + c]     + AF[((r + 8) << 7) + c]     + acc[mi][j][2];
                float v3 = ST[(r + 8) * 132 + c + 1] + AF[((r + 8) << 7) + c + 1] + acc[mi][j][3];
                *(float2*)(ST + r * 132 + c)       = make_float2(v0, v1);
                *(float2*)(ST + (r + 8) * 132 + c) = make_float2(v2, v3);
                *(uint32_t*)(smc + CH_AH + ((r * LDA + c) << 1))       = pack_bf2(v0, v1);
                *(uint32_t*)(smc + CH_AH + (((r + 8) * LDA + c) << 1)) = pack_bf2(v2, v3);
            }
        __syncthreads();
    }
    {
        const float* D2 = g_Dl + (size_t)(b * 3 + 2) * MATSZ;
        for (int idx = t; idx < 4096; idx += 512) {
            int row = idx >> 5, c0 = (idx & 31) << 2;
            int eo = (row * LDA + c0) << 1;
            float4 v2 = *(const float4*)(D2 + (row << 7) + c0);
            *(float4*)(AF + (row << 7) + c0) = v2;
            *(uint32_t*)(smc + CH_DH + eo)     = pack_bf2(v2.x, v2.y);
            *(uint32_t*)(smc + CH_DH + eo + 4) = pack_bf2(v2.z, v2.w);
        }
        __syncthreads();
        float acc[2][4][4];
        #pragma unroll
        for (int mi = 0; mi < 2; mi++)
            #pragma unroll
            for (int j = 0; j < 4; j++)
                #pragma unroll
                for (int q = 0; q < 4; q++) acc[mi][j][q] = 0.f;
        mma128w16(sb + CH_AH, sb + CH_DH, acc, lane, wid);
        #pragma unroll
        for (int mi = 0; mi < 2; mi++)
            #pragma unroll
            for (int j = 0; j < 4; j++) {
                int r = m0 + (mi << 4) + (lane >> 2);
                int c = n0 + (j << 3) + ((lane & 3) << 1);
                ST[r * 132 + c]           += AF[(r << 7) + c]           + acc[mi][j][0];
                ST[r * 132 + c + 1]       += AF[(r << 7) + c + 1]       + acc[mi][j][1];
                ST[(r + 8) * 132 + c]     += AF[((r + 8) << 7) + c]     + acc[mi][j][2];
                ST[(r + 8) * 132 + c + 1] += AF[((r + 8) << 7) + c + 1] + acc[mi][j][3];
            }
        __syncthreads();
    }
    for (int idx = t; idx < 8192; idx += 512) {
        int reg = idx & 1;
        int ln = (idx >> 1) & 31;
        int jg = (idx >> 6) & 15;
        int ks = idx >> 10;
        int k0 = ks * 16 + ((ln & 3) << 1) + reg * 8;
        int n = jg * 8 + (ln >> 2);
        g_frag[(size_t)b * 8192 + idx] = pack_bf2(ST[k0 * 132 + n], ST[(k0 + 1) * 132 + n]);
    }
}

// ---------------- 6) apply: 8x 64-row tiles per CTA; x prefetch in registers ----------------
__global__ __launch_bounds__(256, 2) void apply_kernel(const float* __restrict__ x,
                                                       float* __restrict__ y) {
    extern __shared__ char smc[];
    uint32_t sb = smem_u32(smc);
    int t = threadIdx.x, lane = t & 31, wid = t >> 5;
    int sg = blockIdx.x, b = blockIdx.y;
    int st0 = sg * AP_TILES;

    {
        const uint4* src = (const uint4*)(g_frag + (size_t)b * 8192);
        uint4* dst = (uint4*)(smc + AP_FR);
        for (int i = t; i < 2048; i += 256) dst[i] = src[i];
    }

    int m0 = (wid & 1) << 5, n0 = (wid >> 1) << 5;
    int arow = lane & 15, acol = (lane >> 4) << 3;
    int jgbase = (wid >> 1) << 2;
    int prow = t >> 5, pc0 = (t & 31) << 2;

    float4 pf[8];
    {
        const float* xp = x + ((size_t)b * S_ + (size_t)st0 * 64) * D_;
        #pragma unroll
        for (int i = 0; i < 8; i++)
            pf[i] = *(const float4*)(xp + ((prow + i * 8) << 7) + pc0);
    }

    #pragma unroll 1
    for (int tile = 0; tile < AP_TILES; tile++) {
        const float* xcur = x + ((size_t)b * S_ + (size_t)(st0 + tile) * 64) * D_;
        __syncthreads();
        #pragma unroll
        for (int i = 0; i < 8; i++) {
            int eo = ((prow + i * 8) * LDA + pc0) << 1;
            *(uint32_t*)(smc + AP_XH + eo)     = pack_bf2(pf[i].x, pf[i].y);
            *(uint32_t*)(smc + AP_XH + eo + 4) = pack_bf2(pf[i].z, pf[i].w);
        }
        __syncthreads();
        if (tile + 1 < AP_TILES) {
            const float* xn = x + ((size_t)b * S_ + (size_t)(st0 + tile + 1) * 64) * D_;
            #pragma unroll
            for (int i = 0; i < 8; i++)
                pf[i] = *(const float4*)(xn + ((prow + i * 8) << 7) + pc0);
        }

        float acc[2][4][4];
        #pragma unroll
        for (int mi = 0; mi < 2; mi++)
            #pragma unroll
            for (int j = 0; j < 4; j++)
                #pragma unroll
                for (int q = 0; q < 4; q++) acc[mi][j][q] = 0.f;

        #pragma unroll
        for (int ks = 0; ks < 8; ks++) {
            int k0 = ks << 4;
            uint2 bfr[4];
            #pragma unroll
            for (int j = 0; j < 4; j++)
                bfr[j] = *(const uint2*)(smc + AP_FR +
                          (((ks * 16 + jgbase + j) * 32 + lane) << 3));
            uint32_t a0[4], a1[4];
            ldsm_x4(a0, sb + AP_XH + (uint32_t)(((m0 + arow) * LDA + k0 + acol) << 1));
            ldsm_x4(a1, sb + AP_XH + (uint32_t)(((m0 + 16 + arow) * LDA + k0 + acol) << 1));
            #pragma unroll
            for (int j = 0; j < 4; j++) {
                mma16816(acc[0][j], a0, (const uint32_t*)&bfr[j]);
                mma16816(acc[1][j], a1, (const uint32_t*)&bfr[j]);
            }
        }

        float* yp = y + ((size_t)b * S_ + (size_t)(st0 + tile) * 64) * D_;
        #pragma unroll
        for (int mi = 0; mi < 2; mi++)
            #pragma unroll
            for (int j = 0; j < 4; j++) {
                int r = m0 + (mi << 4) + (lane >> 2);
                int c = n0 + (j << 3) + ((lane & 3) << 1);
                float2 xv = *(const float2*)(xcur + (r << 7) + c);
                *(float2*)(yp + (r << 7) + c) =
                    make_float2(acc[mi][j][0] + xv.x, acc[mi][j][1] + xv.y);
                xv = *(const float2*)(xcur + ((r + 8) << 7) + c);
                *(float2*)(yp + ((r + 8) << 7) + c) =
                    make_float2(acc[mi][j][2] + xv.x, acc[mi][j][3] + xv.y);
            }
    }
}

// ---------------- launch ----------------
extern "C" void kernel_launch(void* const* d_in, const int* in_sizes, int n_in,
                              void* d_out, int out_size) {
    const float* x  = (const float*)d_in[0];
    const float* W1 = (const float*)d_in[1];
    const float* b1 = (const float*)d_in[2];
    const float* W2 = (const float*)d_in[3];
    const float* b2 = (const float*)d_in[4];
    float* y = (float*)d_out;

    cudaFuncSetAttribute(pgemm_tc_kernel, cudaFuncAttributeMaxDynamicSharedMemorySize, PG_TOTAL);
    cudaFuncSetAttribute(expm_chain_kernel, cudaFuncAttributeMaxDynamicSharedMemorySize, CH_TOTAL);
    cudaFuncSetAttribute(combine_kernel, cudaFuncAttributeMaxDynamicSharedMemorySize, CH_TOTAL);
    cudaFuncSetAttribute(apply_kernel, cudaFuncAttributeMaxDynamicSharedMemorySize, AP_TOTAL);

    dummy_kernel<<<1, 32>>>();   // keeps ncu capture slot on pgemm
    mean_partial_kernel<<<dim3(NCHUNK, B_), 256>>>(x);
    h_kernel<<<B_, H_>>>(W1, b1);
    pgemm_tc_kernel<<<W2ROWS / 128, 256, PG_TOTAL>>>(W2, b2);
    expm_chain_kernel<<<NMAT, 512, CH_TOTAL>>>();
    combine_kernel<<<B_, 512, CH_TOTAL>>>();
    apply_kernel<<<dim3(S_ / 64 / AP_TILES, B_), 256, AP_TOTAL>>>(x, y);
}

// round 16
// speedup vs baseline: 1.0683x; 1.0683x over previous
#include <cuda_runtime.h>
#include <cuda_bf16.h>
#include <math.h>
#include <stdint.h>

#define B_    16
#define S_    8192
#define D_    128
#define H_    512
#define NROT  3
#define NMAT  (B_ * NROT)          // 48
#define MATSZ (D_ * D_)            // 16384
#define W2ROWS (NROT * D_ * D_)    // 49152
#define NCHUNK 16

// ---------------- scratch ----------------
__device__ float g_partial[B_ * NCHUNK * D_];
__device__ float g_h[B_ * H_];
__device__ float g_P[B_ * W2ROWS];          // P[b][r]
__device__ float g_Dl[NMAT * MATSZ];        // Delta = expm(g) - I per matrix
__device__ uint32_t g_frag[B_ * 8192];      // bf16 B-fragments of Delta_R per batch

// ---------------- mma.sync / ldmatrix helpers ----------------
__device__ __forceinline__ uint32_t smem_u32(const void* p) {
    uint32_t a;
    asm("{ .reg .u64 t; cvta.to.shared.u64 t, %1; cvt.u32.u64 %0, t; }" : "=r"(a) : "l"(p));
    return a;
}
__device__ __forceinline__ void ldsm_x4(uint32_t* r, uint32_t addr) {
    asm volatile("ldmatrix.sync.aligned.m8n8.x4.shared.b16 {%0,%1,%2,%3}, [%4];"
                 : "=r"(r[0]), "=r"(r[1]), "=r"(r[2]), "=r"(r[3]) : "r"(addr));
}
__device__ __forceinline__ void ldsm_x2_trans(uint32_t* r, uint32_t addr) {
    asm volatile("ldmatrix.sync.aligned.m8n8.x2.trans.shared.b16 {%0,%1}, [%2];"
                 : "=r"(r[0]), "=r"(r[1]) : "r"(addr));
}
__device__ __forceinline__ void mma16816(float* c, const uint32_t* a, const uint32_t* b) {
    asm volatile("mma.sync.aligned.m16n8k16.row.col.f32.bf16.bf16.f32 "
                 "{%0,%1,%2,%3}, {%4,%5,%6,%7}, {%8,%9}, {%0,%1,%2,%3};"
                 : "+f"(c[0]), "+f"(c[1]), "+f"(c[2]), "+f"(c[3])
                 : "r"(a[0]), "r"(a[1]), "r"(a[2]), "r"(a[3]), "r"(b[0]), "r"(b[1]));
}
__device__ __forceinline__ uint32_t pack_bf2(float a, float b) {
    __nv_bfloat162 h = __floats2bfloat162_rn(a, b);
    return *reinterpret_cast<uint32_t*>(&h);
}

#define LDA 136                      // bf16 full-A plane row stride (elements)
// column-split chain smem layout (bytes)
#define C2_AH 0                      // bf16 A full [128][136]            34816
#define C2_DH 34816                  // bf16 Delta slice [128][72]        18432
#define C2_AF 53248                  // fp32 A slice [128][64]            32768
#define C2_ST 86016                  // fp32 staging [128][132] (P load)  67584
#define C2_TOTAL 153600
#define LDB2 72
// combine smem layout (full-width, as before)
#define CH_AH 0
#define CH_DH 34816
#define CH_AF 69632
#define CH_ST 135168
#define CH_TOTAL 202752
// apply smem
#define AP_FR 0
#define AP_XH 32768
#define AP_TOTAL (32768 + 64 * LDA * 2)   // 50176
#define AP_TILES 8
// pgemm smem (R13 proven config)
#define PG_LDB 72
#define PG_BUF2 (128 * PG_LDB * 2)       // 18432
#define PG_HBF  (2 * PG_BUF2)            // 36864
#define PG_TOTAL (PG_HBF + 16 * 260 * 4) // 53504

// dummy no-op kernel: keeps ncu capture slot on pgemm
__global__ void dummy_kernel() {}

// 16-warp (512 thr) full 128x128x128 bf16 MMA (combine kernel)
__device__ __forceinline__ void mma128w16(uint32_t pa, uint32_t pb,
                                          float acc[2][4][4], int lane, int wid) {
    int m0 = (wid & 3) << 5, n0 = (wid >> 2) << 5;
    int arow = lane & 15, acol = (lane >> 4) << 3;
    #pragma unroll
    for (int ks = 0; ks < 8; ks++) {
        int k0 = ks << 4;
        uint32_t a0[4], a1[4];
        ldsm_x4(a0, pa + (uint32_t)(((m0 + arow) * LDA + k0 + acol) << 1));
        ldsm_x4(a1, pa + (uint32_t)(((m0 + 16 + arow) * LDA + k0 + acol) << 1));
        uint32_t bfr[4][2];
        #pragma unroll
        for (int j = 0; j < 4; j++)
            ldsm_x2_trans(bfr[j], pb + (uint32_t)(((k0 + arow) * LDA + n0 + (j << 3)) << 1));
        #pragma unroll
        for (int j = 0; j < 4; j++) {
            mma16816(acc[0][j], a0, bfr[j]);
            mma16816(acc[1][j], a1, bfr[j]);
        }
    }
}

// ---------------- 1) mean over S ----------------
__global__ void mean_partial_kernel(const float* __restrict__ x) {
    int b = blockIdx.y, chunk = blockIdx.x;
    int t = threadIdx.x, lane = t & 31, grp = t >> 5;
    const float* xp = x + ((size_t)b * S_ + (size_t)chunk * 512 + grp) * D_ + lane * 4;
    float4 s = make_float4(0.f, 0.f, 0.f, 0.f);
    #pragma unroll 8
    for (int i = 0; i < 64; i++) {
        float4 v = *(const float4*)xp;
        s.x += v.x; s.y += v.y; s.z += v.z; s.w += v.w;
        xp += 8 * D_;
    }
    __shared__ float4 red[256];
    red[t] = s;
    __syncthreads();
    if (grp < 4) {
        float4 o = red[t + 128];
        red[t] = make_float4(red[t].x + o.x, red[t].y + o.y, red[t].z + o.z, red[t].w + o.w);
    }
    __syncthreads();
    if (grp < 2) {
        float4 o = red[t + 64];
        red[t] = make_float4(red[t].x + o.x, red[t].y + o.y, red[t].z + o.z, red[t].w + o.w);
    }
    __syncthreads();
    if (grp == 0) {
        float4 o = red[t + 32];
        float4 r = make_float4(red[t].x + o.x, red[t].y + o.y, red[t].z + o.z, red[t].w + o.w);
        *(float4*)&g_partial[(b * NCHUNK + chunk) * D_ + lane * 4] = r;
    }
}

// ---------------- 2) h = gelu(pooled @ W1^T + b1) ----------------
__global__ void h_kernel(const float* __restrict__ W1, const float* __restrict__ b1) {
    int b = blockIdx.x, t = threadIdx.x;
    __shared__ float ps[D_];
    if (t < D_) {
        float s = 0.f;
        #pragma unroll
        for (int c = 0; c < NCHUNK; c++) s += g_partial[(b * NCHUNK + c) * D_ + t];
        ps[t] = s * (1.0f / (float)S_);
    }
    __syncthreads();
    float acc = b1[t];
    const float* w = W1 + (size_t)t * D_;
    #pragma unroll 8
    for (int k = 0; k < D_; k++) acc = fmaf(ps[k], w[k], acc);
    float z = acc;
    g_h[b * H_ + t] = 0.5f * z * (1.0f + erff(z * 0.70710678118654752f));
}

// ---------------- 3) pgemm: R13 proven version (128-row tiles, double-buffered) ----------
__global__ __launch_bounds__(256) void pgemm_tc_kernel(const float* __restrict__ W2,
                                                       const float* __restrict__ b2) {
    extern __shared__ char smc[];
    uint32_t sb = smem_u32(smc);
    uint32_t* hbf = (uint32_t*)(smc + PG_HBF);
    int t = threadIdx.x, lane = t & 31, wid = t >> 5;
    int row0 = blockIdx.x * 128;

    for (int idx = t; idx < 16 * 256; idx += 256) {
        int n = idx >> 8, kp = idx & 255;
        float2 v = *(const float2*)&g_h[n * H_ + kp * 2];
        hbf[n * 260 + kp] = pack_bf2(v.x, v.y);
    }

    float4 pf[8];
    #pragma unroll
    for (int i = 0; i < 8; i++) {
        int idx = t + (i << 8);
        int row = idx >> 4, k4 = (idx & 15) << 2;
        pf[i] = *(const float4*)&W2[(size_t)(row0 + row) * H_ + k4];
    }

    float acc[2][4] = {};
    int mrow = lane & 15, mcol = (lane >> 4) << 3;

    for (int sc = 0; sc < 8; sc++) {
        char* buf = smc + (sc & 1) * PG_BUF2;
        #pragma unroll
        for (int i = 0; i < 8; i++) {
            int idx = t + (i << 8);
            int row = idx >> 4, k4 = (idx & 15) << 2;
            int eo = (row * PG_LDB + k4) << 1;
            *(uint32_t*)(buf + eo)     = pack_bf2(pf[i].x, pf[i].y);
            *(uint32_t*)(buf + eo + 4) = pack_bf2(pf[i].z, pf[i].w);
        }
        __syncthreads();
        if (sc < 7) {
            #pragma unroll
            for (int i = 0; i < 8; i++) {
                int idx = t + (i << 8);
                int row = idx >> 4, k4 = (idx & 15) << 2;
                pf[i] = *(const float4*)&W2[(size_t)(row0 + row) * H_ + (sc + 1) * 64 + k4];
            }
        }
        uint32_t bfrag[2][4][2];
        #pragma unroll
        for (int jn = 0; jn < 2; jn++) {
            int n = jn * 8 + (lane >> 2);
            #pragma unroll
            for (int ks = 0; ks < 4; ks++)
                #pragma unroll
                for (int rg = 0; rg < 2; rg++) {
                    int kp = sc * 32 + ks * 8 + rg * 4 + (lane & 3);
                    bfrag[jn][ks][rg] = hbf[n * 260 + kp];
                }
        }
        uint32_t bufb = sb + (sc & 1) * PG_BUF2;
        #pragma unroll
        for (int ks = 0; ks < 4; ks++) {
            uint32_t a[4];
            ldsm_x4(a, bufb + (uint32_t)(((wid * 16 + mrow) * PG_LDB + ks * 16 + mcol) << 1));
            mma16816(acc[0], a, bfrag[0][ks]);
            mma16816(acc[1], a, bfrag[1][ks]);
        }
        __syncthreads();
    }

    #pragma unroll
    for (int mi = 0; mi < 2; mi++) {
        int r = row0 + wid * 16 + mi * 8 + (lane >> 2);
        float bias = b2[r];
        #pragma unroll
        for (int jn = 0; jn < 2; jn++) {
            int b0 = jn * 8 + ((lane & 3) << 1);
            g_P[(size_t)b0 * W2ROWS + r]       = acc[jn][mi * 2]     + bias;
            g_P[(size_t)(b0 + 1) * W2ROWS + r] = acc[jn][mi * 2 + 1] + bias;
        }
    }
}

// ---------------- 4) column-split antisym + expm: grid (48, 2), 512 threads ----------------
// Horner recursion is column-separable: each CTA evolves a 128x64 Delta slice.
__global__ __launch_bounds__(512, 1) void expm_chain_kernel() {
    extern __shared__ char smc[];
    uint32_t sb = smem_u32(smc);
    float* AF = (float*)(smc + C2_AF);    // [128][64] fp32 A slice
    float* ST = (float*)(smc + C2_ST);    // [128][132] P staging, later [128][68] output
    int t = threadIdx.x, lane = t & 31, wid = t >> 5;
    int m = blockIdx.x, cs = blockIdx.y;
    int b = m / NROT, i = m - b * NROT;
    const float* P = g_P + (size_t)b * W2ROWS + (size_t)i * MATSZ;

    // stage full P coalesced
    for (int idx = t; idx < 4096; idx += 512) {
        int row = idx >> 5, c0 = (idx & 31) << 2;
        *(float4*)(ST + row * 132 + c0) = *(const float4*)(P + (row << 7) + c0);
    }
    __syncthreads();
    // A = 0.5*(P - P^T): full bf16 AH; slice fp32 AF + bf16 Delta0 = A/4 into DH
    for (int idx = t; idx < 16384; idx += 512) {
        int d = idx >> 7, e = idx & 127;
        float v = (ST[d * 132 + e] - ST[e * 132 + d]) * 0.5f;
        *(__nv_bfloat16*)(smc + C2_AH + ((d * LDA + e) << 1)) = __float2bfloat16(v);
        if ((e >> 6) == cs) {
            int le = e & 63;
            AF[(d << 6) + le] = v;
            *(__nv_bfloat16*)(smc + C2_DH + ((d * LDB2 + le) << 1)) = __float2bfloat16(v * 0.25f);
        }
    }
    __syncthreads();

    // 16 warps: m0 in 4 groups of 32, n0 in 4 groups of 16 (slice-local)
    int m0 = (wid & 3) << 5, n0 = (wid >> 2) << 4;
    int arow = lane & 15, acol = (lane >> 4) << 3;

    #pragma unroll 1
    for (int step = 0; step < 3; step++) {
        float invc = (step == 0) ? (1.f / 3.f) : (step == 1 ? 0.5f : 1.0f);
        float acc[2][2][4];
        #pragma unroll
        for (int mi = 0; mi < 2; mi++)
            #pragma unroll
            for (int j = 0; j < 2; j++)
                #pragma unroll
                for (int q = 0; q < 4; q++) acc[mi][j][q] = 0.f;
        #pragma unroll
        for (int ks = 0; ks < 8; ks++) {
            int k0 = ks << 4;
            uint32_t a0[4], a1[4];
            ldsm_x4(a0, sb + C2_AH + (uint32_t)(((m0 + arow) * LDA + k0 + acol) << 1));
            ldsm_x4(a1, sb + C2_AH + (uint32_t)(((m0 + 16 + arow) * LDA + k0 + acol) << 1));
            uint32_t bfr[2][2];
            #pragma unroll
            for (int j = 0; j < 2; j++)
                ldsm_x2_trans(bfr[j], sb + C2_DH +
                              (uint32_t)(((k0 + arow) * LDB2 + n0 + (j << 3)) << 1));
            #pragma unroll
            for (int j = 0; j < 2; j++) {
                mma16816(acc[0][j], a0, bfr[j]);
                mma16816(acc[1][j], a1, bfr[j]);
            }
        }
        __syncthreads();   // all reads of DH done before rewrite
        #pragma unroll
        for (int mi = 0; mi < 2; mi++)
            #pragma unroll
            for (int j = 0; j < 2; j++) {
                int r = m0 + (mi << 4) + (lane >> 2);
                int c = n0 + (j << 3) + ((lane & 3) << 1);
                float v0 = (AF[(r << 6) + c]           + acc[mi][j][0]) * invc;
                float v1 = (AF[(r << 6) + c + 1]       + acc[mi][j][1]) * invc;
                float v2 = (AF[((r + 8) << 6) + c]     + acc[mi][j][2]) * invc;
                float v3 = (AF[((r + 8) << 6) + c + 1] + acc[mi][j][3]) * invc;
                if (step < 2) {
                    *(uint32_t*)(smc + C2_DH + ((r * LDB2 + c) << 1))       = pack_bf2(v0, v1);
                    *(uint32_t*)(smc + C2_DH + (((r + 8) * LDB2 + c) << 1)) = pack_bf2(v2, v3);
                } else {
                    *(float2*)(ST + r * 68 + c)       = make_float2(v0, v1);
                    *(float2*)(ST + (r + 8) * 68 + c) = make_float2(v2, v3);
                }
            }
        __syncthreads();
    }

    // write slice to g_Dl
    float* out = g_Dl + (size_t)m * MATSZ + (cs << 6);
    for (int idx = t; idx < 2048; idx += 512) {
        int row = idx >> 4, c0 = (idx & 15) << 2;
        *(float4*)(out + (row << 7) + c0) = *(const float4*)(ST + row * 68 + c0);
    }
}

// ---------------- 5) combine (512 threads): Delta_R; emit frags ----------------
__global__ __launch_bounds__(512, 1) void combine_kernel() {
    extern __shared__ char smc[];
    uint32_t sb = smem_u32(smc);
    float* AF = (float*)(smc + CH_AF);
    float* ST = (float*)(smc + CH_ST);
    int t = threadIdx.x, lane = t & 31, wid = t >> 5;
    int b = blockIdx.x;
    int m0 = (wid & 3) << 5, n0 = (wid >> 2) << 5;

    {
        const float* D0 = g_Dl + (size_t)(b * 3 + 0) * MATSZ;
        const float* D1 = g_Dl + (size_t)(b * 3 + 1) * MATSZ;
        for (int idx = t; idx < 4096; idx += 512) {
            int row = idx >> 5, c0 = (idx & 31) << 2;
            int eo = (row * LDA + c0) << 1;
            float4 v0 = *(const float4*)(D0 + (row << 7) + c0);
            *(float4*)(AF + (row << 7) + c0) = v0;
            *(uint32_t*)(smc + CH_AH + eo)     = pack_bf2(v0.x, v0.y);
            *(uint32_t*)(smc + CH_AH + eo + 4) = pack_bf2(v0.z, v0.w);
            float4 v1 = *(const float4*)(D1 + (row << 7) + c0);
            *(float4*)(ST + row * 132 + c0) = v1;
            *(uint32_t*)(smc + CH_DH + eo)     = pack_bf2(v1.x, v1.y);
            *(uint32_t*)(smc + CH_DH + eo + 4) = pack_bf2(v1.z, v1.w);
        }
        __syncthreads();
        float acc[2][4][4];
        #pragma unroll
        for (int mi = 0; mi < 2; mi++)
            #pragma unroll
            for (int j = 0; j < 4; j++)
                #pragma unroll
                for (int q = 0; q < 4; q++) acc[mi][j][q] = 0.f;
        mma128w16(sb + CH_AH, sb + CH_DH, acc, lane, wid);
        __syncthreads();
        #pragma unroll
        for (int mi = 0; mi < 2; mi++)
            #pragma unroll
            for (int j = 0; j < 4; j++) {
                int r = m0 + (mi << 4) + (lane >> 2);
                int c = n0 + (j << 3) + ((lane & 3) << 1);
                float v0 = ST[r * 132 + c]           + AF[(r << 7) + c]           + acc[mi][j][0];
                float v1 = ST[r * 132 + c + 1]       + AF[(r << 7) + c + 1]       + acc[mi][j][1];
                float v2 = ST[(r + 8) * 132 + c]     + AF[((r + 8) << 7) + c]     + acc[mi][j][2];
                float v3 = ST[(r + 8) * 132 + c + 1] + AF[((r + 8) << 7) + c + 1] + acc[mi][j][3];
                *(float2*)(ST + r * 132 + c)       = make_float2(v0, v1);
                *(float2*)(ST + (r + 8) * 132 + c) = make_float2(v2, v3);
                *(uint32_t*)(smc + CH_AH + ((r * LDA + c) << 1))       = pack_bf2(v0, v1);
                *(uint32_t*)(smc + CH_AH + (((r + 8) * LDA + c) << 1)) = pack_bf2(v2, v3);
            }
        __syncthreads();
    }
    {
        const float* D2 = g_Dl + (size_t)(b * 3 + 2) * MATSZ;
        for (int idx = t; idx < 4096; idx += 512) {
            int row = idx >> 5, c0 = (idx & 31) << 2;
            int eo = (row * LDA + c0) << 1;
            float4 v2 = *(const float4*)(D2 + (row << 7) + c0);
            *(float4*)(AF + (row << 7) + c0) = v2;
            *(uint32_t*)(smc + CH_DH + eo)     = pack_bf2(v2.x, v2.y);
            *(uint32_t*)(smc + CH_DH + eo + 4) = pack_bf2(v2.z, v2.w);
        }
        __syncthreads();
        float acc[2][4][4];
        #pragma unroll
        for (int mi = 0; mi < 2; mi++)
            #pragma unroll
            for (int j = 0; j < 4; j++)
                #pragma unroll
                for (int q = 0; q < 4; q++) acc[mi][j][q] = 0.f;
        mma128w16(sb + CH_AH, sb + CH_DH, acc, lane, wid);
        #pragma unroll
        for (int mi = 0; mi < 2; mi++)
            #pragma unroll
            for (int j = 0; j < 4; j++) {
                int r = m0 + (mi << 4) + (lane >> 2);
                int c = n0 + (j << 3) + ((lane & 3) << 1);
                ST[r * 132 + c]           += AF[(r << 7) + c]           + acc[mi][j][0];
                ST[r * 132 + c + 1]       += AF[(r << 7) + c + 1]       + acc[mi][j][1];
                ST[(r + 8) * 132 + c]     += AF[((r + 8) << 7) + c]     + acc[mi][j][2];
                ST[(r + 8) * 132 + c + 1] += AF[((r + 8) << 7) + c + 1] + acc[mi][j][3];
            }
        __syncthreads();
    }
    for (int idx = t; idx < 8192; idx += 512) {
        int reg = idx & 1;
        int ln = (idx >> 1) & 31;
        int jg = (idx >> 6) & 15;
        int ks = idx >> 10;
        int k0 = ks * 16 + ((ln & 3) << 1) + reg * 8;
        int n = jg * 8 + (ln >> 2);
        g_frag[(size_t)b * 8192 + idx] = pack_bf2(ST[k0 * 132 + n], ST[(k0 + 1) * 132 + n]);
    }
}

// ---------------- 6) apply: 8x 64-row tiles per CTA; x prefetch in registers ----------------
__global__ __launch_bounds__(256, 2) void apply_kernel(const float* __restrict__ x,
                                                       float* __restrict__ y) {
    extern __shared__ char smc[];
    uint32_t sb = smem_u32(smc);
    int t = threadIdx.x, lane = t & 31, wid = t >> 5;
    int sg = blockIdx.x, b = blockIdx.y;
    int st0 = sg * AP_TILES;

    {
        const uint4* src = (const uint4*)(g_frag + (size_t)b * 8192);
        uint4* dst = (uint4*)(smc + AP_FR);
        for (int i = t; i < 2048; i += 256) dst[i] = src[i];
    }

    int m0 = (wid & 1) << 5, n0 = (wid >> 1) << 5;
    int arow = lane & 15, acol = (lane >> 4) << 3;
    int jgbase = (wid >> 1) << 2;
    int prow = t >> 5, pc0 = (t & 31) << 2;

    float4 pf[8];
    {
        const float* xp = x + ((size_t)b * S_ + (size_t)st0 * 64) * D_;
        #pragma unroll
        for (int i = 0; i < 8; i++)
            pf[i] = *(const float4*)(xp + ((prow + i * 8) << 7) + pc0);
    }

    #pragma unroll 1
    for (int tile = 0; tile < AP_TILES; tile++) {
        const float* xcur = x + ((size_t)b * S_ + (size_t)(st0 + tile) * 64) * D_;
        __syncthreads();
        #pragma unroll
        for (int i = 0; i < 8; i++) {
            int eo = ((prow + i * 8) * LDA + pc0) << 1;
            *(uint32_t*)(smc + AP_XH + eo)     = pack_bf2(pf[i].x, pf[i].y);
            *(uint32_t*)(smc + AP_XH + eo + 4) = pack_bf2(pf[i].z, pf[i].w);
        }
        __syncthreads();
        if (tile + 1 < AP_TILES) {
            const float* xn = x + ((size_t)b * S_ + (size_t)(st0 + tile + 1) * 64) * D_;
            #pragma unroll
            for (int i = 0; i < 8; i++)
                pf[i] = *(const float4*)(xn + ((prow + i * 8) << 7) + pc0);
        }

        float acc[2][4][4];
        #pragma unroll
        for (int mi = 0; mi < 2; mi++)
            #pragma unroll
            for (int j = 0; j < 4; j++)
                #pragma unroll
                for (int q = 0; q < 4; q++) acc[mi][j][q] = 0.f;

        #pragma unroll
        for (int ks = 0; ks < 8; ks++) {
            int k0 = ks << 4;
            uint2 bfr[4];
            #pragma unroll
            for (int j = 0; j < 4; j++)
                bfr[j] = *(const uint2*)(smc + AP_FR +
                          (((ks * 16 + jgbase + j) * 32 + lane) << 3));
            uint32_t a0[4], a1[4];
            ldsm_x4(a0, sb + AP_XH + (uint32_t)(((m0 + arow) * LDA + k0 + acol) << 1));
            ldsm_x4(a1, sb + AP_XH + (uint32_t)(((m0 + 16 + arow) * LDA + k0 + acol) << 1));
            #pragma unroll
            for (int j = 0; j < 4; j++) {
                mma16816(acc[0][j], a0, (const uint32_t*)&bfr[j]);
                mma16816(acc[1][j], a1, (const uint32_t*)&bfr[j]);
            }
        }

        float* yp = y + ((size_t)b * S_ + (size_t)(st0 + tile) * 64) * D_;
        #pragma unroll
        for (int mi = 0; mi < 2; mi++)
            #pragma unroll
            for (int j = 0; j < 4; j++) {
                int r = m0 + (mi << 4) + (lane >> 2);
                int c = n0 + (j << 3) + ((lane & 3) << 1);
                float2 xv = *(const float2*)(xcur + (r << 7) + c);
                *(float2*)(yp + (r << 7) + c) =
                    make_float2(acc[mi][j][0] + xv.x, acc[mi][j][1] + xv.y);
                xv = *(const float2*)(xcur + ((r + 8) << 7) + c);
                *(float2*)(yp + ((r + 8) << 7) + c) =
                    make_float2(acc[mi][j][2] + xv.x, acc[mi][j][3] + xv.y);
            }
    }
}

// ---------------- launch ----------------
extern "C" void kernel_launch(void* const* d_in, const int* in_sizes, int n_in,
                              void* d_out, int out_size) {
    const float* x  = (const float*)d_in[0];
    const float* W1 = (const float*)d_in[1];
    const float* b1 = (const float*)d_in[2];
    const float* W2 = (const float*)d_in[3];
    const float* b2 = (const float*)d_in[4];
    float* y = (float*)d_out;

    cudaFuncSetAttribute(pgemm_tc_kernel, cudaFuncAttributeMaxDynamicSharedMemorySize, PG_TOTAL);
    cudaFuncSetAttribute(expm_chain_kernel, cudaFuncAttributeMaxDynamicSharedMemorySize, C2_TOTAL);
    cudaFuncSetAttribute(combine_kernel, cudaFuncAttributeMaxDynamicSharedMemorySize, CH_TOTAL);
    cudaFuncSetAttribute(apply_kernel, cudaFuncAttributeMaxDynamicSharedMemorySize, AP_TOTAL);

    dummy_kernel<<<1, 32>>>();   // keeps ncu capture slot on pgemm
    mean_partial_kernel<<<dim3(NCHUNK, B_), 256>>>(x);
    h_kernel<<<B_, H_>>>(W1, b1);
    pgemm_tc_kernel<<<W2ROWS / 128, 256, PG_TOTAL>>>(W2, b2);
    expm_chain_kernel<<<dim3(NMAT, 2), 512, C2_TOTAL>>>();
    combine_kernel<<<B_, 512, CH_TOTAL>>>();
    apply_kernel<<<dim3(S_ / 64 / AP_TILES, B_), 256, AP_TOTAL>>>(x, y);
}